// round 1
// baseline (speedup 1.0000x reference)
#include <cuda_runtime.h>

// Problem constants
#define Bn 8
#define Cn 4
#define Hn 64
#define Wn 2048
#define HWn (Hn * Wn)          // 131072
#define CHWn (Cn * HWn)        // 524288

// Tile config
#define TX 128
#define TY 8
#define HX (TX + 4)            // 132 (halo +-2 in W)
#define HY (TY + 2)            // 10  (halo +-1 in H)
#define HALO (HX * HY)         // 1320
#define NTHREADS 256

// Gaussian smoothness weights: exp(-(dh^2+dw^2)/(2*0.9^2)), center = 0
#define W1 0.53940751f   // d2 = 1
#define W2 0.29096046f   // d2 = 2
#define W4 0.08465798f   // d2 = 4
#define W5 0.04566517f   // d2 = 5

// -1 / (2 * 0.015^2)
#define NEG_INV_2TB2 (-2222.2222222f)

// Ping-pong scratch (allocation is forbidden -> device global)
__device__ float g_scratch[Bn * CHWn];

__global__ __launch_bounds__(NTHREADS)
void crf_iter(const float* __restrict__ Qin,
              const float* __restrict__ unary,
              const float* __restrict__ xyz,
              const float* __restrict__ mask,
              const float* __restrict__ wapp,
              const float* __restrict__ wsmo,
              const float* __restrict__ compat,
              float* __restrict__ Qout)
{
    __shared__ float sP0[HALO], sP1[HALO], sP2[HALO], sP3[HALO];
    __shared__ float sM[HALO];
    __shared__ float sX[HALO], sY[HALO], sZ[HALO];

    const int b   = blockIdx.z;
    const int ty0 = blockIdx.y * TY;
    const int tx0 = blockIdx.x * TX;
    const int tid = threadIdx.x;

    const float* __restrict__ Qb = Qin  + b * CHWn;
    const float* __restrict__ Xb = xyz  + b * 3 * HWn;
    const float* __restrict__ Mb = mask + b * HWn;

    // ---- Phase 1: load halo tile, softmax over C into smem ----
    for (int i = tid; i < HALO; i += NTHREADS) {
        const int hy = i / HX;
        const int hx = i - hy * HX;
        const int gy = ty0 + hy - 1;
        const int gx = tx0 + hx - 2;
        float p0 = 0.f, p1 = 0.f, p2 = 0.f, p3 = 0.f;
        float m = 0.f, x = 0.f, y = 0.f, z = 0.f;
        if (gy >= 0 && gy < Hn && gx >= 0 && gx < Wn) {
            const int g = gy * Wn + gx;
            const float q0 = Qb[g];
            const float q1 = Qb[g + HWn];
            const float q2 = Qb[g + 2 * HWn];
            const float q3 = Qb[g + 3 * HWn];
            const float mx = fmaxf(fmaxf(q0, q1), fmaxf(q2, q3));
            p0 = __expf(q0 - mx);
            p1 = __expf(q1 - mx);
            p2 = __expf(q2 - mx);
            p3 = __expf(q3 - mx);
            const float inv = 1.0f / (p0 + p1 + p2 + p3);
            p0 *= inv; p1 *= inv; p2 *= inv; p3 *= inv;
            m = Mb[g];
            x = Xb[g];
            y = Xb[g + HWn];
            z = Xb[g + 2 * HWn];
        }
        sP0[i] = p0; sP1[i] = p1; sP2[i] = p2; sP3[i] = p3;
        sM[i] = m; sX[i] = x; sY[i] = y; sZ[i] = z;
    }

    // Per-channel weights + compatibility matrix (uniform loads)
    const float wa0 = wapp[0], wa1 = wapp[1], wa2 = wapp[2], wa3 = wapp[3];
    const float ws0 = wsmo[0], ws1 = wsmo[1], ws2 = wsmo[2], ws3 = wsmo[3];
    const float c00 = compat[0],  c01 = compat[1],  c02 = compat[2],  c03 = compat[3];
    const float c10 = compat[4],  c11 = compat[5],  c12 = compat[6],  c13 = compat[7];
    const float c20 = compat[8],  c21 = compat[9],  c22 = compat[10], c23 = compat[11];
    const float c30 = compat[12], c31 = compat[13], c32 = compat[14], c33 = compat[15];

    __syncthreads();

    // ---- Phase 2: fused 14-tap conv + appearance + compat update ----
    const int offs[14] = {
        -HX - 2, -HX - 1, -HX, -HX + 1, -HX + 2,
              -2,      -1,           1,       2,
         HX - 2,  HX - 1,  HX,  HX + 1,  HX + 2
    };
    const float wts[14] = {
        W5, W2, W1, W2, W5,
        W4, W1, W1, W4,
        W5, W2, W1, W2, W5
    };

    #pragma unroll
    for (int k = 0; k < (TX * TY) / NTHREADS; ++k) {
        const int p  = tid + k * NTHREADS;
        const int ty = p / TX;
        const int tx = p - ty * TX;
        const int base = (ty + 1) * HX + (tx + 2);

        const float ax = sX[base], ay = sY[base], az = sZ[base];

        float s0 = 0.f, s1 = 0.f, s2 = 0.f, s3 = 0.f;   // smoothness conv
        float a0 = 0.f, a1 = 0.f, a2 = 0.f, a3 = 0.f;   // appearance accum

        #pragma unroll
        for (int t = 0; t < 14; ++t) {
            const int nb = base + offs[t];
            const float wt = wts[t];
            const float dx = sX[nb] - ax;
            const float dy = sY[nb] - ay;
            const float dz = sZ[nb] - az;
            float pd = dx * dx;
            pd = fmaf(dy, dy, pd);
            pd = fmaf(dz, dz, pd);
            const float bm = __expf(pd * NEG_INV_2TB2) * sM[nb];
            const float q0 = sP0[nb], q1 = sP1[nb], q2 = sP2[nb], q3 = sP3[nb];
            s0 = fmaf(wt, q0, s0);
            s1 = fmaf(wt, q1, s1);
            s2 = fmaf(wt, q2, s2);
            s3 = fmaf(wt, q3, s3);
            a0 = fmaf(bm, q0, a0);
            a1 = fmaf(bm, q1, a1);
            a2 = fmaf(bm, q2, a2);
            a3 = fmaf(bm, q3, a3);
        }

        // exp_app = a * m_center ; weighted_k = s * (ws + wa * exp_app)
        const float mC = sM[base];
        a0 *= mC; a1 *= mC; a2 *= mC; a3 *= mC;
        const float wk0 = s0 * fmaf(wa0, a0, ws0);
        const float wk1 = s1 * fmaf(wa1, a1, ws1);
        const float wk2 = s2 * fmaf(wa2, a2, ws2);
        const float wk3 = s3 * fmaf(wa3, a3, ws3);

        // pairwise[o] = sum_c compat[o][c] * wk[c]
        const float pw0 = c00 * wk0 + c01 * wk1 + c02 * wk2 + c03 * wk3;
        const float pw1 = c10 * wk0 + c11 * wk1 + c12 * wk2 + c13 * wk3;
        const float pw2 = c20 * wk0 + c21 * wk1 + c22 * wk2 + c23 * wk3;
        const float pw3 = c30 * wk0 + c31 * wk1 + c32 * wk2 + c33 * wk3;

        const int g = b * CHWn + (ty0 + ty) * Wn + (tx0 + tx);
        Qout[g]           = unary[g]           - pw0;
        Qout[g + HWn]     = unary[g + HWn]     - pw1;
        Qout[g + 2 * HWn] = unary[g + 2 * HWn] - pw2;
        Qout[g + 3 * HWn] = unary[g + 3 * HWn] - pw3;
    }
}

extern "C" void kernel_launch(void* const* d_in, const int* in_sizes, int n_in,
                              void* d_out, int out_size)
{
    const float* unary  = (const float*)d_in[0];
    const float* xyz    = (const float*)d_in[1];
    const float* mask   = (const float*)d_in[2];
    const float* wapp   = (const float*)d_in[3];
    const float* wsmo   = (const float*)d_in[4];
    const float* compat = (const float*)d_in[5];
    float* out = (float*)d_out;

    float* scratch = nullptr;
    cudaGetSymbolAddress((void**)&scratch, g_scratch);

    dim3 grid(Wn / TX, Hn / TY, Bn);
    dim3 block(NTHREADS);

    // iter 1: unary -> out ; iter 2: out -> scratch ; iter 3: scratch -> out
    crf_iter<<<grid, block>>>(unary,   unary, xyz, mask, wapp, wsmo, compat, out);
    crf_iter<<<grid, block>>>(out,     unary, xyz, mask, wapp, wsmo, compat, scratch);
    crf_iter<<<grid, block>>>(scratch, unary, xyz, mask, wapp, wsmo, compat, out);
}

// round 2
// speedup vs baseline: 1.0567x; 1.0567x over previous
#include <cuda_runtime.h>

// Problem constants
#define Bn 8
#define Cn 4
#define Hn 64
#define Wn 2048
#define HWn (Hn * Wn)          // 131072
#define CHWn (Cn * HWn)        // 524288

// Tile config
#define TX 128
#define TY 8
#define HX (TX + 4)            // 132 (halo +-2 in W)
#define HY (TY + 2)            // 10  (halo +-1 in H)
#define HALO (HX * HY)         // 1320
#define NTHREADS 256

// Gaussian smoothness weights: exp(-(dh^2+dw^2)/(2*0.9^2)), center = 0
#define W1 0.53940751f   // d2 = 1
#define W2 0.29096046f   // d2 = 2
#define W4 0.08465798f   // d2 = 4
#define W5 0.04566517f   // d2 = 5

// C2 = -1/(2*0.015^2) * log2(e)  (exp(x) == exp2(x*log2e))
#define C2f      (-3206.0005353f)
#define NEG2C2f  (6412.0010706f)     // -2 * C2
#define L2Ef     (1.4426950408889634f)
#define MASK_BIG (1.0e9f)

// Ping-pong scratch, packed float4 per pixel (allocation forbidden -> device globals)
__device__ float4 g_scratchA[Bn * HWn];
__device__ float4 g_scratchB[Bn * HWn];

// ---- packed f32x2 helpers (sm_10x) ----
__device__ __forceinline__ unsigned long long pk2(float lo, float hi) {
    unsigned long long r;
    asm("mov.b64 %0, {%1, %2};" : "=l"(r) : "f"(lo), "f"(hi));
    return r;
}
__device__ __forceinline__ void upk2(unsigned long long v, float& lo, float& hi) {
    asm("mov.b64 {%0, %1}, %2;" : "=f"(lo), "=f"(hi) : "l"(v));
}
__device__ __forceinline__ unsigned long long ffma2(unsigned long long a,
                                                    unsigned long long b,
                                                    unsigned long long c) {
    unsigned long long d;
    asm("fma.rn.f32x2 %0, %1, %2, %3;" : "=l"(d) : "l"(a), "l"(b), "l"(c));
    return d;
}
__device__ __forceinline__ float ex2(float x) {
    float r;
    asm("ex2.approx.ftz.f32 %0, %1;" : "=f"(r) : "f"(x));
    return r;
}

template<bool IN_PACKED, bool OUT_PACKED>
__global__ __launch_bounds__(NTHREADS)
void crf_iter(const float*  __restrict__ QinPlanar,
              const float4* __restrict__ QinPacked,
              const float*  __restrict__ unary,
              const float*  __restrict__ xyz,
              const float*  __restrict__ mask,
              const float*  __restrict__ wapp,
              const float*  __restrict__ wsmo,
              const float*  __restrict__ compat,
              float*        __restrict__ OutPlanar,
              float4*       __restrict__ OutPacked)
{
    __shared__ float4 sQ[HALO];   // softmaxed probs (p0,p1,p2,p3)
    __shared__ float4 sG[HALO];   // (x, y, z, |xyz|^2*C2 + (m-1)*BIG)

    const int b   = blockIdx.z;
    const int ty0 = blockIdx.y * TY;
    const int tx0 = blockIdx.x * TX;
    const int tid = threadIdx.x;

    const float* __restrict__ Xb = xyz  + b * 3 * HWn;
    const float* __restrict__ Mb = mask + b * HWn;

    // ---- Phase 1: load halo tile, softmax over C, fold geometry ----
    for (int i = tid; i < HALO; i += NTHREADS) {
        const int hy = i / HX;
        const int hx = i - hy * HX;
        const int gy = ty0 + hy - 1;
        const int gx = tx0 + hx - 2;
        float4 sq = make_float4(0.f, 0.f, 0.f, 0.f);
        float4 sg = make_float4(0.f, 0.f, 0.f, -MASK_BIG);
        if (gy >= 0 && gy < Hn && gx >= 0 && gx < Wn) {
            const int g = gy * Wn + gx;
            float q0, q1, q2, q3;
            if (IN_PACKED) {
                const float4 q = QinPacked[b * HWn + g];
                q0 = q.x; q1 = q.y; q2 = q.z; q3 = q.w;
            } else {
                const float* Qb = QinPlanar + b * CHWn;
                q0 = Qb[g];
                q1 = Qb[g + HWn];
                q2 = Qb[g + 2 * HWn];
                q3 = Qb[g + 3 * HWn];
            }
            const float mx = fmaxf(fmaxf(q0, q1), fmaxf(q2, q3));
            float p0 = ex2((q0 - mx) * L2Ef);
            float p1 = ex2((q1 - mx) * L2Ef);
            float p2 = ex2((q2 - mx) * L2Ef);
            float p3 = ex2((q3 - mx) * L2Ef);
            const float inv = __fdividef(1.0f, p0 + p1 + p2 + p3);
            sq.x = p0 * inv; sq.y = p1 * inv; sq.z = p2 * inv; sq.w = p3 * inv;

            const float x = Xb[g];
            const float y = Xb[g + HWn];
            const float z = Xb[g + 2 * HWn];
            const float m = Mb[g];
            float nrm = x * x;
            nrm = fmaf(y, y, nrm);
            nrm = fmaf(z, z, nrm);
            sg.x = x; sg.y = y; sg.z = z;
            // |n|^2*C2 + (m-1)*BIG  (m in {0,1}; masked -> arg <= -1e9 -> exp2 = 0)
            sg.w = fmaf(nrm, C2f, fmaf(m, MASK_BIG, -MASK_BIG));
        }
        sQ[i] = sq;
        sG[i] = sg;
    }

    // Per-channel weights + compatibility matrix (uniform)
    const float wa0 = wapp[0], wa1 = wapp[1], wa2 = wapp[2], wa3 = wapp[3];
    const float ws0 = wsmo[0], ws1 = wsmo[1], ws2 = wsmo[2], ws3 = wsmo[3];
    const float c00 = compat[0],  c01 = compat[1],  c02 = compat[2],  c03 = compat[3];
    const float c10 = compat[4],  c11 = compat[5],  c12 = compat[6],  c13 = compat[7];
    const float c20 = compat[8],  c21 = compat[9],  c22 = compat[10], c23 = compat[11];
    const float c30 = compat[12], c31 = compat[13], c32 = compat[14], c33 = compat[15];

    __syncthreads();

    // Packed tap weights (only 4 distinct values)
    const unsigned long long w1p = pk2(W1, W1);
    const unsigned long long w2p = pk2(W2, W2);
    const unsigned long long w4p = pk2(W4, W4);
    const unsigned long long w5p = pk2(W5, W5);

    // ---- Phase 2: fused 14-tap conv + appearance + compat update ----
    #pragma unroll
    for (int k = 0; k < (TX * TY) / NTHREADS; ++k) {
        const int p  = tid + k * NTHREADS;
        const int ty = p / TX;
        const int tx = p - ty * TX;
        const int base = (ty + 1) * HX + (tx + 2);

        const float4 ga = sG[base];
        const float axs = ga.x * NEG2C2f;
        const float ays = ga.y * NEG2C2f;
        const float azs = ga.z * NEG2C2f;
        const float na  = ga.w;                       // |a|^2*C2 (mask-folded)
        const float mC  = (na > -1.0e8f) ? 1.0f : 0.0f;  // recover center mask

        unsigned long long s01 = 0ull, s23 = 0ull;   // smoothness conv accum
        unsigned long long a01 = 0ull, a23 = 0ull;   // appearance accum

        const int offs[14] = {
            -HX - 2, -HX - 1, -HX, -HX + 1, -HX + 2,
                  -2,      -1,           1,       2,
             HX - 2,  HX - 1,  HX,  HX + 1,  HX + 2
        };
        const unsigned long long wtp[14] = {
            w5p, w2p, w1p, w2p, w5p,
            w4p, w1p, w1p, w4p,
            w5p, w2p, w1p, w2p, w5p
        };

        #pragma unroll
        for (int t = 0; t < 14; ++t) {
            const int nb = base + offs[t];
            const float4 gn = sG[nb];
            // arg = C2 * (|n-a|^2)  [+ mask folds]  via expansion, fully pre-scaled
            const float arg = fmaf(gn.x, axs,
                              fmaf(gn.y, ays,
                              fmaf(gn.z, azs, gn.w + na)));
            const float bm = ex2(arg);               // beta * m_nb (exact 0 if masked)
            const ulonglong2 q2 = *reinterpret_cast<const ulonglong2*>(&sQ[nb]);
            const unsigned long long bm2 = pk2(bm, bm);
            s01 = ffma2(wtp[t], q2.x, s01);
            s23 = ffma2(wtp[t], q2.y, s23);
            a01 = ffma2(bm2,    q2.x, a01);
            a23 = ffma2(bm2,    q2.y, a23);
        }

        float s0, s1, s2, s3, a0, a1, a2, a3;
        upk2(s01, s0, s1); upk2(s23, s2, s3);
        upk2(a01, a0, a1); upk2(a23, a2, a3);

        // exp_app = a * m_center ; weighted_k = s * (ws + wa * exp_app)
        a0 *= mC; a1 *= mC; a2 *= mC; a3 *= mC;
        const float wk0 = s0 * fmaf(wa0, a0, ws0);
        const float wk1 = s1 * fmaf(wa1, a1, ws1);
        const float wk2 = s2 * fmaf(wa2, a2, ws2);
        const float wk3 = s3 * fmaf(wa3, a3, ws3);

        // pairwise[o] = sum_c compat[o][c] * wk[c]
        const float pw0 = c00 * wk0 + c01 * wk1 + c02 * wk2 + c03 * wk3;
        const float pw1 = c10 * wk0 + c11 * wk1 + c12 * wk2 + c13 * wk3;
        const float pw2 = c20 * wk0 + c21 * wk1 + c22 * wk2 + c23 * wk3;
        const float pw3 = c30 * wk0 + c31 * wk1 + c32 * wk2 + c33 * wk3;

        const int g = (ty0 + ty) * Wn + (tx0 + tx);
        const int gg = b * CHWn + g;
        const float u0 = unary[gg];
        const float u1 = unary[gg + HWn];
        const float u2 = unary[gg + 2 * HWn];
        const float u3 = unary[gg + 3 * HWn];

        if (OUT_PACKED) {
            OutPacked[b * HWn + g] = make_float4(u0 - pw0, u1 - pw1, u2 - pw2, u3 - pw3);
        } else {
            OutPlanar[gg]           = u0 - pw0;
            OutPlanar[gg + HWn]     = u1 - pw1;
            OutPlanar[gg + 2 * HWn] = u2 - pw2;
            OutPlanar[gg + 3 * HWn] = u3 - pw3;
        }
    }
}

extern "C" void kernel_launch(void* const* d_in, const int* in_sizes, int n_in,
                              void* d_out, int out_size)
{
    const float* unary  = (const float*)d_in[0];
    const float* xyz    = (const float*)d_in[1];
    const float* mask   = (const float*)d_in[2];
    const float* wapp   = (const float*)d_in[3];
    const float* wsmo   = (const float*)d_in[4];
    const float* compat = (const float*)d_in[5];
    float* out = (float*)d_out;

    float4* sA = nullptr;
    float4* sB = nullptr;
    cudaGetSymbolAddress((void**)&sA, g_scratchA);
    cudaGetSymbolAddress((void**)&sB, g_scratchB);

    dim3 grid(Wn / TX, Hn / TY, Bn);
    dim3 block(NTHREADS);

    // iter 1: unary(planar) -> scratchA(packed)
    crf_iter<false, true><<<grid, block>>>(unary, nullptr, unary, xyz, mask,
                                           wapp, wsmo, compat, nullptr, sA);
    // iter 2: scratchA(packed) -> scratchB(packed)
    crf_iter<true, true><<<grid, block>>>(nullptr, sA, unary, xyz, mask,
                                          wapp, wsmo, compat, nullptr, sB);
    // iter 3: scratchB(packed) -> out(planar)
    crf_iter<true, false><<<grid, block>>>(nullptr, sB, unary, xyz, mask,
                                           wapp, wsmo, compat, out, nullptr);
}